// round 11
// baseline (speedup 1.0000x reference)
#include <cuda_runtime.h>
#include <cstdint>

#define MAXN 50000
#define MAXE 1600000
#define CAP  128   // bucket capacity per dst; Poisson(32) max-degree ~65, 2x margin

// Scratch (device globals — no allocation allowed)
__device__ __align__(16) float g_h1[MAXN * 64];    // layer1 features fp32
__device__ __align__(16) float g_es1[MAXN * 2];
__device__ __align__(16) float g_ed1[MAXN * 2];
__device__ __align__(16) float g_acc1[MAXN * 64];  // layer1 output (relu'd)
__device__ __align__(16) float g_h2[MAXN * 32];    // layer2 features fp32
__device__ __align__(16) float g_es2[MAXN];
__device__ __align__(16) float g_ed2[MAXN];

// Bucketed adjacency (by destination); self-loops handled inline in agg
__device__ int g_wr[MAXN];            // per-dst fill counter (= in-degree)
__device__ int g_srt[MAXN * CAP];     // src ids, bucket d at [d*CAP, d*CAP+deg)

static __device__ __forceinline__ float lrelu(float v) {
    return v > 0.0f ? v : 0.2f * v;
}

// ---- packed f32x2 helpers (sm_103a 2x fp32 path) ----
static __device__ __forceinline__ unsigned long long dup2(float v) {
    unsigned long long r; unsigned u = __float_as_uint(v);
    asm("mov.b64 %0, {%1, %1};" : "=l"(r) : "r"(u));
    return r;
}
static __device__ __forceinline__ unsigned long long fma2(
    unsigned long long a, unsigned long long b, unsigned long long c) {
    unsigned long long d;
    asm("fma.rn.f32x2 %0, %1, %2, %3;" : "=l"(d) : "l"(a), "l"(b), "l"(c));
    return d;
}
static __device__ __forceinline__ float2 unpk(unsigned long long v) {
    unsigned lo, hi;
    asm("mov.b64 {%0, %1}, %2;" : "=r"(lo), "=r"(hi) : "l"(v));
    return make_float2(__uint_as_float(lo), __uint_as_float(hi));
}

// ---------------------------------------------------------------------------
// Zero bucket counters
// ---------------------------------------------------------------------------
__global__ void zero_wr_kernel(int n) {
    int i = blockIdx.x * blockDim.x + threadIdx.x;
    if (i < n) g_wr[i] = 0;
}

// ---------------------------------------------------------------------------
// Scatter edges into fixed-capacity dst buckets (8 edges/thread, MLP 8)
// ---------------------------------------------------------------------------
__global__ void scatter_kernel(const int* __restrict__ ei, int E) {
    int base = (blockIdx.x * blockDim.x + threadIdx.x) * 8;
    if (base + 8 <= E) {
        int4 sa = *reinterpret_cast<const int4*>(ei + base);
        int4 sb = *reinterpret_cast<const int4*>(ei + base + 4);
        int4 da = *reinterpret_cast<const int4*>(ei + E + base);
        int4 db = *reinterpret_cast<const int4*>(ei + E + base + 4);
        int p0 = atomicAdd(&g_wr[da.x], 1);
        int p1 = atomicAdd(&g_wr[da.y], 1);
        int p2 = atomicAdd(&g_wr[da.z], 1);
        int p3 = atomicAdd(&g_wr[da.w], 1);
        int p4 = atomicAdd(&g_wr[db.x], 1);
        int p5 = atomicAdd(&g_wr[db.y], 1);
        int p6 = atomicAdd(&g_wr[db.z], 1);
        int p7 = atomicAdd(&g_wr[db.w], 1);
        if (p0 < CAP) g_srt[da.x * CAP + p0] = sa.x;
        if (p1 < CAP) g_srt[da.y * CAP + p1] = sa.y;
        if (p2 < CAP) g_srt[da.z * CAP + p2] = sa.z;
        if (p3 < CAP) g_srt[da.w * CAP + p3] = sa.w;
        if (p4 < CAP) g_srt[db.x * CAP + p4] = sb.x;
        if (p5 < CAP) g_srt[db.y * CAP + p5] = sb.y;
        if (p6 < CAP) g_srt[db.z * CAP + p6] = sb.z;
        if (p7 < CAP) g_srt[db.w * CAP + p7] = sb.w;
    } else {
        for (int k = base; k < E; k++) {
            int d = ei[E + k];
            int p = atomicAdd(&g_wr[d], 1);
            if (p < CAP) g_srt[d * CAP + p] = ei[k];
        }
    }
}

// ---------------------------------------------------------------------------
// GEMM1 + scores1 fused: h1[N,64] = x[N,128] @ W1[128,64] (f32x2 FMA),
// per-head src/dst scores in epilogue.
// ---------------------------------------------------------------------------
__global__ void gemm1_kernel(const float* __restrict__ x, const float* __restrict__ W,
                             const float* __restrict__ a_src, const float* __restrict__ a_dst,
                             int n) {
    __shared__ __align__(16) float As[16][64];
    __shared__ __align__(16) float Bs[16][64];
    const int t = threadIdx.x;
    const int row0 = blockIdx.x * 64;
    const int tr = t >> 4, tc = t & 15;
    const int lm = t & 63, lk = (t >> 6) << 2;
    const int bk = t >> 4, bn = (t & 15) << 2;
    unsigned long long acc2[4][2] = {};
    const int r = row0 + lm;

    for (int kt = 0; kt < 128; kt += 16) {
        float4 av = make_float4(0.f, 0.f, 0.f, 0.f);
        if (r < n) av = *reinterpret_cast<const float4*>(x + (size_t)r * 128 + kt + lk);
        As[lk + 0][lm] = av.x; As[lk + 1][lm] = av.y;
        As[lk + 2][lm] = av.z; As[lk + 3][lm] = av.w;
        *reinterpret_cast<float4*>(&Bs[bk][bn]) =
            *reinterpret_cast<const float4*>(W + (size_t)(kt + bk) * 64 + bn);
        __syncthreads();
        #pragma unroll
        for (int kk = 0; kk < 16; kk++) {
            float4 a4 = *reinterpret_cast<const float4*>(&As[kk][tr << 2]);
            unsigned long long b01 =
                *reinterpret_cast<const unsigned long long*>(&Bs[kk][tc << 2]);
            unsigned long long b23 =
                *reinterpret_cast<const unsigned long long*>(&Bs[kk][(tc << 2) + 2]);
            unsigned long long a0 = dup2(a4.x), a1 = dup2(a4.y),
                               a2 = dup2(a4.z), a3 = dup2(a4.w);
            acc2[0][0] = fma2(a0, b01, acc2[0][0]); acc2[0][1] = fma2(a0, b23, acc2[0][1]);
            acc2[1][0] = fma2(a1, b01, acc2[1][0]); acc2[1][1] = fma2(a1, b23, acc2[1][1]);
            acc2[2][0] = fma2(a2, b01, acc2[2][0]); acc2[2][1] = fma2(a2, b23, acc2[2][1]);
            acc2[3][0] = fma2(a3, b01, acc2[3][0]); acc2[3][1] = fma2(a3, b23, acc2[3][1]);
        }
        __syncthreads();
    }

    float accf[4][4];
    #pragma unroll
    for (int i = 0; i < 4; i++) {
        float2 lo = unpk(acc2[i][0]);
        float2 hi = unpk(acc2[i][1]);
        accf[i][0] = lo.x; accf[i][1] = lo.y;
        accf[i][2] = hi.x; accf[i][3] = hi.y;
    }

    #pragma unroll
    for (int i = 0; i < 4; i++) {
        int rr = row0 + (tr << 2) + i;
        if (rr < n)
            *reinterpret_cast<float4*>(g_h1 + (size_t)rr * 64 + (tc << 2)) =
                make_float4(accf[i][0], accf[i][1], accf[i][2], accf[i][3]);
    }

    // fused scores: cols 4tc..4tc+3, head = tc>>3. Reduce over 8-lane groups.
    float4 as4 = *reinterpret_cast<const float4*>(a_src + (tc << 2));
    float4 ad4 = *reinterpret_cast<const float4*>(a_dst + (tc << 2));
    #pragma unroll
    for (int i = 0; i < 4; i++) {
        float sp = accf[i][0] * as4.x + accf[i][1] * as4.y + accf[i][2] * as4.z + accf[i][3] * as4.w;
        float dp = accf[i][0] * ad4.x + accf[i][1] * ad4.y + accf[i][2] * ad4.z + accf[i][3] * ad4.w;
        #pragma unroll
        for (int off = 1; off < 8; off <<= 1) {
            sp += __shfl_xor_sync(0xffffffffu, sp, off);
            dp += __shfl_xor_sync(0xffffffffu, dp, off);
        }
        int rr = row0 + (tr << 2) + i;
        if ((tc & 7) == 0 && rr < n) {
            int head = tc >> 3;
            g_es1[rr * 2 + head] = sp;
            g_ed1[rr * 2 + head] = dp;
        }
    }
}

// ---------------------------------------------------------------------------
// agg1: one warp per dst; 2 edges per warp-instruction (16-lane groups);
// lane covers 4 fp32 channels of ITS OWN head only; single exp per lane.
// ---------------------------------------------------------------------------
__global__ void agg1_kernel(const float* __restrict__ b1, int n) {
    int gid = blockIdx.x * blockDim.x + threadIdx.x;
    int node = gid >> 5, lane = gid & 31;
    if (node >= n) return;
    const int grp = lane >> 4;
    const int sub = lane & 15;
    const int head = sub >> 3;
    const int coff = head * 32 + (sub & 7) * 4;
    const int* __restrict__ srt = g_srt;
    const float* __restrict__ es1 = g_es1;
    const float* __restrict__ h1 = g_h1;
    int deg = g_wr[node]; if (deg > CAP) deg = CAP;
    int beg = node * CAP, end = beg + deg;
    const float edh = g_ed1[2 * node + head];

    float den;
    float4 acc;
    {
        float p = __expf(lrelu(es1[2 * node + head] + edh));
        if (grp) p = 0.f;
        den = p;
        float4 hv = *reinterpret_cast<const float4*>(h1 + (size_t)node * 64 + coff);
        acc.x = p * hv.x; acc.y = p * hv.y; acc.z = p * hv.z; acc.w = p * hv.w;
    }

    int i = beg;
    for (; i + 4 <= end; i += 4) {
        int sA = srt[i + grp];
        int sB = srt[i + 2 + grp];
        float eA = es1[2 * sA + head];
        float eB = es1[2 * sB + head];
        float4 hA = *reinterpret_cast<const float4*>(h1 + (size_t)sA * 64 + coff);
        float4 hB = *reinterpret_cast<const float4*>(h1 + (size_t)sB * 64 + coff);
        float pA = __expf(lrelu(eA + edh));
        float pB = __expf(lrelu(eB + edh));
        den += pA + pB;
        acc.x = fmaf(pA, hA.x, acc.x); acc.y = fmaf(pA, hA.y, acc.y);
        acc.z = fmaf(pA, hA.z, acc.z); acc.w = fmaf(pA, hA.w, acc.w);
        acc.x = fmaf(pB, hB.x, acc.x); acc.y = fmaf(pB, hB.y, acc.y);
        acc.z = fmaf(pB, hB.z, acc.z); acc.w = fmaf(pB, hB.w, acc.w);
    }
    for (; i < end; i += 2) {
        int ii = i + grp;
        bool v = ii < end;
        int s = v ? srt[ii] : node;
        float e = es1[2 * s + head];
        float4 hv = *reinterpret_cast<const float4*>(h1 + (size_t)s * 64 + coff);
        float p = v ? __expf(lrelu(e + edh)) : 0.f;
        den += p;
        acc.x = fmaf(p, hv.x, acc.x); acc.y = fmaf(p, hv.y, acc.y);
        acc.z = fmaf(p, hv.z, acc.z); acc.w = fmaf(p, hv.w, acc.w);
    }

    den   += __shfl_xor_sync(0xffffffffu, den,   16);
    acc.x += __shfl_xor_sync(0xffffffffu, acc.x, 16);
    acc.y += __shfl_xor_sync(0xffffffffu, acc.y, 16);
    acc.z += __shfl_xor_sync(0xffffffffu, acc.z, 16);
    acc.w += __shfl_xor_sync(0xffffffffu, acc.w, 16);

    if (lane < 16) {
        float inv = 1.0f / (den + 1e-16f);
        float4 bb = *reinterpret_cast<const float4*>(b1 + coff);
        float4 o;
        o.x = fmaf(acc.x, inv, bb.x); o.x = o.x > 0.f ? o.x : 0.f;
        o.y = fmaf(acc.y, inv, bb.y); o.y = o.y > 0.f ? o.y : 0.f;
        o.z = fmaf(acc.z, inv, bb.z); o.z = o.z > 0.f ? o.z : 0.f;
        o.w = fmaf(acc.w, inv, bb.w); o.w = o.w > 0.f ? o.w : 0.f;
        *reinterpret_cast<float4*>(g_acc1 + (size_t)node * 64 + coff) = o;
    }
}

// ---------------------------------------------------------------------------
// GEMM2 + scores2 fused: one warp per row; k-packed f32x2 FMA.
// W2 packed once per block: (W2[2k][j], W2[2k+1][j]) adjacent.
// ---------------------------------------------------------------------------
__global__ void gemm2_kernel(const float* __restrict__ W2,
                             const float* __restrict__ a_src,
                             const float* __restrict__ a_dst, int n) {
    __shared__ __align__(16) float W2p[2048];  // [k2*64 + 2j + (k&1)]
    for (int idx = threadIdx.x; idx < 2048; idx += blockDim.x) {
        int k = idx >> 5, j = idx & 31;
        W2p[(k >> 1) * 64 + (j << 1) + (k & 1)] = W2[idx];
    }
    __syncthreads();
    int gid = blockIdx.x * blockDim.x + threadIdx.x;
    int row = gid >> 5, lane = gid & 31;
    if (row >= n) return;
    const float* a = g_acc1 + (size_t)row * 64;
    unsigned long long sum2 = 0;
    #pragma unroll
    for (int k2 = 0; k2 < 32; k2++) {
        unsigned long long a2 = *reinterpret_cast<const unsigned long long*>(a + (k2 << 1));
        unsigned long long w2 = *reinterpret_cast<const unsigned long long*>(
            W2p + (k2 << 6) + (lane << 1));
        sum2 = fma2(a2, w2, sum2);
    }
    float2 sh = unpk(sum2);
    float sum = sh.x + sh.y;
    g_h2[(size_t)row * 32 + lane] = sum;
    float s = sum * a_src[lane];
    float d = sum * a_dst[lane];
    #pragma unroll
    for (int off = 16; off; off >>= 1) {
        s += __shfl_xor_sync(0xffffffffu, s, off);
        d += __shfl_xor_sync(0xffffffffu, d, off);
    }
    if (lane == 0) { g_es2[row] = s; g_ed2[row] = d; }
}

// ---------------------------------------------------------------------------
// agg2: one warp per dst; 4 edges per warp-instruction (8-lane groups, fp32)
// ---------------------------------------------------------------------------
__global__ void agg2_kernel(const float* __restrict__ b2, int n, float* __restrict__ out) {
    int gid = blockIdx.x * blockDim.x + threadIdx.x;
    int node = gid >> 5, lane = gid & 31;
    if (node >= n) return;
    const int grp = lane >> 3;
    const int coff = (lane & 7) * 4;
    const int* __restrict__ srt = g_srt;
    const float* __restrict__ es2 = g_es2;
    const float* __restrict__ h2 = g_h2;
    int deg = g_wr[node]; if (deg > CAP) deg = CAP;
    int beg = node * CAP, end = beg + deg;
    float edv = g_ed2[node];

    float den;
    float4 acc;
    {
        float p = __expf(lrelu(es2[node] + edv));
        if (grp) p = 0.f;
        den = p;
        float4 hv = *reinterpret_cast<const float4*>(h2 + (size_t)node * 32 + coff);
        acc.x = p * hv.x; acc.y = p * hv.y; acc.z = p * hv.z; acc.w = p * hv.w;
    }

    int i = beg;
    for (; i + 8 <= end; i += 8) {
        int sA = srt[i + grp];
        int sB = srt[i + 4 + grp];
        float eA = es2[sA];
        float eB = es2[sB];
        float4 hA = *reinterpret_cast<const float4*>(h2 + (size_t)sA * 32 + coff);
        float4 hB = *reinterpret_cast<const float4*>(h2 + (size_t)sB * 32 + coff);
        float pA = __expf(lrelu(eA + edv));
        float pB = __expf(lrelu(eB + edv));
        den += pA + pB;
        acc.x = fmaf(pA, hA.x, acc.x); acc.y = fmaf(pA, hA.y, acc.y);
        acc.z = fmaf(pA, hA.z, acc.z); acc.w = fmaf(pA, hA.w, acc.w);
        acc.x = fmaf(pB, hB.x, acc.x); acc.y = fmaf(pB, hB.y, acc.y);
        acc.z = fmaf(pB, hB.z, acc.z); acc.w = fmaf(pB, hB.w, acc.w);
    }
    for (; i < end; i += 4) {
        int ii = i + grp;
        bool v = ii < end;
        int s = v ? srt[ii] : node;
        float e = es2[s];
        float4 hv = *reinterpret_cast<const float4*>(h2 + (size_t)s * 32 + coff);
        float p = v ? __expf(lrelu(e + edv)) : 0.f;
        den += p;
        acc.x = fmaf(p, hv.x, acc.x); acc.y = fmaf(p, hv.y, acc.y);
        acc.z = fmaf(p, hv.z, acc.z); acc.w = fmaf(p, hv.w, acc.w);
    }

    #pragma unroll
    for (int off = 8; off <= 16; off <<= 1) {
        den   += __shfl_xor_sync(0xffffffffu, den,   off);
        acc.x += __shfl_xor_sync(0xffffffffu, acc.x, off);
        acc.y += __shfl_xor_sync(0xffffffffu, acc.y, off);
        acc.z += __shfl_xor_sync(0xffffffffu, acc.z, off);
        acc.w += __shfl_xor_sync(0xffffffffu, acc.w, off);
    }

    if (lane < 8) {
        float inv = 1.0f / (den + 1e-16f);
        float4 bb = *reinterpret_cast<const float4*>(b2 + coff);
        float4 o;
        o.x = fmaf(acc.x, inv, bb.x);
        o.y = fmaf(acc.y, inv, bb.y);
        o.z = fmaf(acc.z, inv, bb.z);
        o.w = fmaf(acc.w, inv, bb.w);
        *reinterpret_cast<float4*>(out + (size_t)node * 32 + coff) = o;
    }
}

// ---------------------------------------------------------------------------
extern "C" void kernel_launch(void* const* d_in, const int* in_sizes, int n_in,
                              void* d_out, int out_size) {
    const float* x      = (const float*)d_in[0];
    const int*   ei     = (const int*)d_in[1];
    const float* W1     = (const float*)d_in[2];
    const float* a_src1 = (const float*)d_in[3];
    const float* a_dst1 = (const float*)d_in[4];
    const float* b1     = (const float*)d_in[5];
    const float* W2     = (const float*)d_in[6];
    const float* a_src2 = (const float*)d_in[7];
    const float* a_dst2 = (const float*)d_in[8];
    const float* b2     = (const float*)d_in[9];
    float* out = (float*)d_out;

    const int n  = in_sizes[0] / 128;   // 50000
    const int E  = in_sizes[1] / 2;     // 1600000
    const int e8 = (E + 7) / 8;

    // One-time side stream + fork/join events (host objects; no device alloc).
    static cudaStream_t s2 = nullptr;
    static cudaEvent_t evFork = nullptr, evJoin = nullptr;
    if (!s2) {
        cudaStreamCreateWithFlags(&s2, cudaStreamNonBlocking);
        cudaEventCreateWithFlags(&evFork, cudaEventDisableTiming);
        cudaEventCreateWithFlags(&evJoin, cudaEventDisableTiming);
    }

    // Fork: graph chain (zero+scatter) on s2, feature chain (gemm1) on default.
    cudaEventRecord(evFork, 0);
    cudaStreamWaitEvent(s2, evFork, 0);
    zero_wr_kernel<<<(n + 255) / 256, 256, 0, s2>>>(n);
    scatter_kernel<<<(e8 + 255) / 256, 256, 0, s2>>>(ei, E);
    cudaEventRecord(evJoin, s2);

    gemm1_kernel<<<(n + 63) / 64, 256>>>(x, W1, a_src1, a_dst1, n);

    // Join: agg1 needs both gemm1 (default stream order) and scatter (event).
    cudaStreamWaitEvent(0, evJoin, 0);
    agg1_kernel<<<(n * 32 + 255) / 256, 256>>>(b1, n);

    gemm2_kernel<<<(n * 32 + 255) / 256, 256>>>(W2, a_src2, a_dst2, n);
    agg2_kernel<<<(n * 32 + 255) / 256, 256>>>(b2, n, out);
}

// round 12
// speedup vs baseline: 1.1466x; 1.1466x over previous
#include <cuda_runtime.h>
#include <cstdint>

#define MAXN 50000
#define MAXE 1600000
#define CAP  128   // bucket capacity per dst; Poisson(32) max-degree ~65, 2x margin

// Scratch (device globals — no allocation allowed)
__device__ __align__(16) float g_h1[MAXN * 64];    // layer1 features fp32
__device__ __align__(16) float g_es1[MAXN * 2];
__device__ __align__(16) float g_ed1[MAXN * 2];
__device__ __align__(16) float g_h2[MAXN * 32];    // layer2 features fp32
__device__ __align__(16) float g_es2[MAXN];
__device__ __align__(16) float g_ed2[MAXN];
__device__ __align__(16) float g_W2p[2048];        // packed W2: [k4*128 + j*4 + m] = W2[4k4+m][j]

// Bucketed adjacency (by destination); self-loops handled inline in agg
__device__ int g_wr[MAXN];            // per-dst fill counter (= in-degree)
__device__ int g_srt[MAXN * CAP];     // src ids, bucket d at [d*CAP, d*CAP+deg)

static __device__ __forceinline__ float lrelu(float v) {
    return v > 0.0f ? v : 0.2f * v;
}

// ---- packed f32x2 helpers (sm_103a 2x fp32 path) ----
static __device__ __forceinline__ unsigned long long dup2(float v) {
    unsigned long long r; unsigned u = __float_as_uint(v);
    asm("mov.b64 %0, {%1, %1};" : "=l"(r) : "r"(u));
    return r;
}
static __device__ __forceinline__ unsigned long long fma2(
    unsigned long long a, unsigned long long b, unsigned long long c) {
    unsigned long long d;
    asm("fma.rn.f32x2 %0, %1, %2, %3;" : "=l"(d) : "l"(a), "l"(b), "l"(c));
    return d;
}
static __device__ __forceinline__ float2 unpk(unsigned long long v) {
    unsigned lo, hi;
    asm("mov.b64 {%0, %1}, %2;" : "=r"(lo), "=r"(hi) : "l"(v));
    return make_float2(__uint_as_float(lo), __uint_as_float(hi));
}

// ---------------------------------------------------------------------------
// Zero bucket counters
// ---------------------------------------------------------------------------
__global__ void zero_wr_kernel(int n) {
    int i = blockIdx.x * blockDim.x + threadIdx.x;
    if (i < n) g_wr[i] = 0;
}

// ---------------------------------------------------------------------------
// Pack W2 for the fused gemm2 epilogue: g_W2p[k4*128 + j*4 + m] = W2[4k4+m][j]
// ---------------------------------------------------------------------------
__global__ void pack_w2_kernel(const float* __restrict__ W2) {
    int idx = blockIdx.x * blockDim.x + threadIdx.x;
    if (idx >= 2048) return;
    int k4 = idx >> 7, j = (idx >> 2) & 31, m = idx & 3;
    g_W2p[idx] = W2[(4 * k4 + m) * 32 + j];
}

// ---------------------------------------------------------------------------
// Scatter edges into fixed-capacity dst buckets (8 edges/thread, MLP 8)
// ---------------------------------------------------------------------------
__global__ void scatter_kernel(const int* __restrict__ ei, int E) {
    int base = (blockIdx.x * blockDim.x + threadIdx.x) * 8;
    if (base + 8 <= E) {
        int4 sa = *reinterpret_cast<const int4*>(ei + base);
        int4 sb = *reinterpret_cast<const int4*>(ei + base + 4);
        int4 da = *reinterpret_cast<const int4*>(ei + E + base);
        int4 db = *reinterpret_cast<const int4*>(ei + E + base + 4);
        int p0 = atomicAdd(&g_wr[da.x], 1);
        int p1 = atomicAdd(&g_wr[da.y], 1);
        int p2 = atomicAdd(&g_wr[da.z], 1);
        int p3 = atomicAdd(&g_wr[da.w], 1);
        int p4 = atomicAdd(&g_wr[db.x], 1);
        int p5 = atomicAdd(&g_wr[db.y], 1);
        int p6 = atomicAdd(&g_wr[db.z], 1);
        int p7 = atomicAdd(&g_wr[db.w], 1);
        if (p0 < CAP) g_srt[da.x * CAP + p0] = sa.x;
        if (p1 < CAP) g_srt[da.y * CAP + p1] = sa.y;
        if (p2 < CAP) g_srt[da.z * CAP + p2] = sa.z;
        if (p3 < CAP) g_srt[da.w * CAP + p3] = sa.w;
        if (p4 < CAP) g_srt[db.x * CAP + p4] = sb.x;
        if (p5 < CAP) g_srt[db.y * CAP + p5] = sb.y;
        if (p6 < CAP) g_srt[db.z * CAP + p6] = sb.z;
        if (p7 < CAP) g_srt[db.w * CAP + p7] = sb.w;
    } else {
        for (int k = base; k < E; k++) {
            int d = ei[E + k];
            int p = atomicAdd(&g_wr[d], 1);
            if (p < CAP) g_srt[d * CAP + p] = ei[k];
        }
    }
}

// ---------------------------------------------------------------------------
// GEMM1 + scores1 fused: h1[N,64] = x[N,128] @ W1[128,64] (f32x2 FMA),
// per-head src/dst scores in epilogue.
// ---------------------------------------------------------------------------
__global__ void gemm1_kernel(const float* __restrict__ x, const float* __restrict__ W,
                             const float* __restrict__ a_src, const float* __restrict__ a_dst,
                             int n) {
    __shared__ __align__(16) float As[16][64];
    __shared__ __align__(16) float Bs[16][64];
    const int t = threadIdx.x;
    const int row0 = blockIdx.x * 64;
    const int tr = t >> 4, tc = t & 15;
    const int lm = t & 63, lk = (t >> 6) << 2;
    const int bk = t >> 4, bn = (t & 15) << 2;
    unsigned long long acc2[4][2] = {};
    const int r = row0 + lm;

    for (int kt = 0; kt < 128; kt += 16) {
        float4 av = make_float4(0.f, 0.f, 0.f, 0.f);
        if (r < n) av = *reinterpret_cast<const float4*>(x + (size_t)r * 128 + kt + lk);
        As[lk + 0][lm] = av.x; As[lk + 1][lm] = av.y;
        As[lk + 2][lm] = av.z; As[lk + 3][lm] = av.w;
        *reinterpret_cast<float4*>(&Bs[bk][bn]) =
            *reinterpret_cast<const float4*>(W + (size_t)(kt + bk) * 64 + bn);
        __syncthreads();
        #pragma unroll
        for (int kk = 0; kk < 16; kk++) {
            float4 a4 = *reinterpret_cast<const float4*>(&As[kk][tr << 2]);
            unsigned long long b01 =
                *reinterpret_cast<const unsigned long long*>(&Bs[kk][tc << 2]);
            unsigned long long b23 =
                *reinterpret_cast<const unsigned long long*>(&Bs[kk][(tc << 2) + 2]);
            unsigned long long a0 = dup2(a4.x), a1 = dup2(a4.y),
                               a2 = dup2(a4.z), a3 = dup2(a4.w);
            acc2[0][0] = fma2(a0, b01, acc2[0][0]); acc2[0][1] = fma2(a0, b23, acc2[0][1]);
            acc2[1][0] = fma2(a1, b01, acc2[1][0]); acc2[1][1] = fma2(a1, b23, acc2[1][1]);
            acc2[2][0] = fma2(a2, b01, acc2[2][0]); acc2[2][1] = fma2(a2, b23, acc2[2][1]);
            acc2[3][0] = fma2(a3, b01, acc2[3][0]); acc2[3][1] = fma2(a3, b23, acc2[3][1]);
        }
        __syncthreads();
    }

    float accf[4][4];
    #pragma unroll
    for (int i = 0; i < 4; i++) {
        float2 lo = unpk(acc2[i][0]);
        float2 hi = unpk(acc2[i][1]);
        accf[i][0] = lo.x; accf[i][1] = lo.y;
        accf[i][2] = hi.x; accf[i][3] = hi.y;
    }

    #pragma unroll
    for (int i = 0; i < 4; i++) {
        int rr = row0 + (tr << 2) + i;
        if (rr < n)
            *reinterpret_cast<float4*>(g_h1 + (size_t)rr * 64 + (tc << 2)) =
                make_float4(accf[i][0], accf[i][1], accf[i][2], accf[i][3]);
    }

    // fused scores: cols 4tc..4tc+3, head = tc>>3. Reduce over 8-lane groups.
    float4 as4 = *reinterpret_cast<const float4*>(a_src + (tc << 2));
    float4 ad4 = *reinterpret_cast<const float4*>(a_dst + (tc << 2));
    #pragma unroll
    for (int i = 0; i < 4; i++) {
        float sp = accf[i][0] * as4.x + accf[i][1] * as4.y + accf[i][2] * as4.z + accf[i][3] * as4.w;
        float dp = accf[i][0] * ad4.x + accf[i][1] * ad4.y + accf[i][2] * ad4.z + accf[i][3] * ad4.w;
        #pragma unroll
        for (int off = 1; off < 8; off <<= 1) {
            sp += __shfl_xor_sync(0xffffffffu, sp, off);
            dp += __shfl_xor_sync(0xffffffffu, dp, off);
        }
        int rr = row0 + (tr << 2) + i;
        if ((tc & 7) == 0 && rr < n) {
            int head = tc >> 3;
            g_es1[rr * 2 + head] = sp;
            g_ed1[rr * 2 + head] = dp;
        }
    }
}

// ---------------------------------------------------------------------------
// agg1 + gemm2 + scores2 fused: one warp per dst node.
// Phase 1 (agg): 2 edges per warp-instruction, single-head exp per lane.
// Phase 2 (gemm2): feat staged in per-warp smem; W2 read from pre-packed
// global via LDG.128; f32x2 FMA. No block-wide sync anywhere.
// ---------------------------------------------------------------------------
__global__ void agg1_kernel(const float* __restrict__ b1,
                            const float* __restrict__ a_src2,
                            const float* __restrict__ a_dst2, int n) {
    __shared__ __align__(16) float s_feat[8][64];  // per-warp relu'd node features

    int gid = blockIdx.x * blockDim.x + threadIdx.x;
    int node = gid >> 5, lane = gid & 31;
    int w = threadIdx.x >> 5;
    if (node >= n) return;

    const int grp = lane >> 4;
    const int sub = lane & 15;
    const int head = sub >> 3;
    const int coff = head * 32 + (sub & 7) * 4;
    const int* __restrict__ srt = g_srt;
    const float* __restrict__ es1 = g_es1;
    const float* __restrict__ h1 = g_h1;
    int deg = g_wr[node]; if (deg > CAP) deg = CAP;
    int beg = node * CAP, end = beg + deg;
    const float edh = g_ed1[2 * node + head];

    float den;
    float4 acc;
    {
        float p = __expf(lrelu(es1[2 * node + head] + edh));
        if (grp) p = 0.f;
        den = p;
        float4 hv = *reinterpret_cast<const float4*>(h1 + (size_t)node * 64 + coff);
        acc.x = p * hv.x; acc.y = p * hv.y; acc.z = p * hv.z; acc.w = p * hv.w;
    }

    int i = beg;
    for (; i + 4 <= end; i += 4) {
        int sA = srt[i + grp];
        int sB = srt[i + 2 + grp];
        float eA = es1[2 * sA + head];
        float eB = es1[2 * sB + head];
        float4 hA = *reinterpret_cast<const float4*>(h1 + (size_t)sA * 64 + coff);
        float4 hB = *reinterpret_cast<const float4*>(h1 + (size_t)sB * 64 + coff);
        float pA = __expf(lrelu(eA + edh));
        float pB = __expf(lrelu(eB + edh));
        den += pA + pB;
        acc.x = fmaf(pA, hA.x, acc.x); acc.y = fmaf(pA, hA.y, acc.y);
        acc.z = fmaf(pA, hA.z, acc.z); acc.w = fmaf(pA, hA.w, acc.w);
        acc.x = fmaf(pB, hB.x, acc.x); acc.y = fmaf(pB, hB.y, acc.y);
        acc.z = fmaf(pB, hB.z, acc.z); acc.w = fmaf(pB, hB.w, acc.w);
    }
    for (; i < end; i += 2) {
        int ii = i + grp;
        bool v = ii < end;
        int s = v ? srt[ii] : node;
        float e = es1[2 * s + head];
        float4 hv = *reinterpret_cast<const float4*>(h1 + (size_t)s * 64 + coff);
        float p = v ? __expf(lrelu(e + edh)) : 0.f;
        den += p;
        acc.x = fmaf(p, hv.x, acc.x); acc.y = fmaf(p, hv.y, acc.y);
        acc.z = fmaf(p, hv.z, acc.z); acc.w = fmaf(p, hv.w, acc.w);
    }

    den   += __shfl_xor_sync(0xffffffffu, den,   16);
    acc.x += __shfl_xor_sync(0xffffffffu, acc.x, 16);
    acc.y += __shfl_xor_sync(0xffffffffu, acc.y, 16);
    acc.z += __shfl_xor_sync(0xffffffffu, acc.z, 16);
    acc.w += __shfl_xor_sync(0xffffffffu, acc.w, 16);

    if (lane < 16) {
        float inv = 1.0f / (den + 1e-16f);
        float4 bb = *reinterpret_cast<const float4*>(b1 + coff);
        float4 o;
        o.x = fmaf(acc.x, inv, bb.x); o.x = o.x > 0.f ? o.x : 0.f;
        o.y = fmaf(acc.y, inv, bb.y); o.y = o.y > 0.f ? o.y : 0.f;
        o.z = fmaf(acc.z, inv, bb.z); o.z = o.z > 0.f ? o.z : 0.f;
        o.w = fmaf(acc.w, inv, bb.w); o.w = o.w > 0.f ? o.w : 0.f;
        *reinterpret_cast<float4*>(&s_feat[w][coff]) = o;
    }
    __syncwarp();

    // gemm2: h2[lane] = sum_k feat[k] * W2[k][lane]; W2 pre-packed in global.
    // Per k4: feat quad (16B smem broadcast) x W2 quad (LDG.128), 2x FMA2.
    unsigned long long sum2 = 0;
    const float* feat = s_feat[w];
    #pragma unroll
    for (int k4 = 0; k4 < 16; k4++) {
        ulonglong2 a2 = *reinterpret_cast<const ulonglong2*>(feat + (k4 << 2));
        ulonglong2 w2 = *reinterpret_cast<const ulonglong2*>(g_W2p + (k4 << 7) + (lane << 2));
        sum2 = fma2(a2.x, w2.x, sum2);
        sum2 = fma2(a2.y, w2.y, sum2);
    }
    float2 sh = unpk(sum2);
    float sum = sh.x + sh.y;
    g_h2[(size_t)node * 32 + lane] = sum;

    float s = sum * a_src2[lane];
    float d = sum * a_dst2[lane];
    #pragma unroll
    for (int off = 16; off; off >>= 1) {
        s += __shfl_xor_sync(0xffffffffu, s, off);
        d += __shfl_xor_sync(0xffffffffu, d, off);
    }
    if (lane == 0) { g_es2[node] = s; g_ed2[node] = d; }
}

// ---------------------------------------------------------------------------
// agg2: one warp per dst; 4 edges per warp-instruction (8-lane groups, fp32)
// ---------------------------------------------------------------------------
__global__ void agg2_kernel(const float* __restrict__ b2, int n, float* __restrict__ out) {
    int gid = blockIdx.x * blockDim.x + threadIdx.x;
    int node = gid >> 5, lane = gid & 31;
    if (node >= n) return;
    const int grp = lane >> 3;
    const int coff = (lane & 7) * 4;
    const int* __restrict__ srt = g_srt;
    const float* __restrict__ es2 = g_es2;
    const float* __restrict__ h2 = g_h2;
    int deg = g_wr[node]; if (deg > CAP) deg = CAP;
    int beg = node * CAP, end = beg + deg;
    float edv = g_ed2[node];

    float den;
    float4 acc;
    {
        float p = __expf(lrelu(es2[node] + edv));
        if (grp) p = 0.f;
        den = p;
        float4 hv = *reinterpret_cast<const float4*>(h2 + (size_t)node * 32 + coff);
        acc.x = p * hv.x; acc.y = p * hv.y; acc.z = p * hv.z; acc.w = p * hv.w;
    }

    int i = beg;
    for (; i + 8 <= end; i += 8) {
        int sA = srt[i + grp];
        int sB = srt[i + 4 + grp];
        float eA = es2[sA];
        float eB = es2[sB];
        float4 hA = *reinterpret_cast<const float4*>(h2 + (size_t)sA * 32 + coff);
        float4 hB = *reinterpret_cast<const float4*>(h2 + (size_t)sB * 32 + coff);
        float pA = __expf(lrelu(eA + edv));
        float pB = __expf(lrelu(eB + edv));
        den += pA + pB;
        acc.x = fmaf(pA, hA.x, acc.x); acc.y = fmaf(pA, hA.y, acc.y);
        acc.z = fmaf(pA, hA.z, acc.z); acc.w = fmaf(pA, hA.w, acc.w);
        acc.x = fmaf(pB, hB.x, acc.x); acc.y = fmaf(pB, hB.y, acc.y);
        acc.z = fmaf(pB, hB.z, acc.z); acc.w = fmaf(pB, hB.w, acc.w);
    }
    for (; i < end; i += 4) {
        int ii = i + grp;
        bool v = ii < end;
        int s = v ? srt[ii] : node;
        float e = es2[s];
        float4 hv = *reinterpret_cast<const float4*>(h2 + (size_t)s * 32 + coff);
        float p = v ? __expf(lrelu(e + edv)) : 0.f;
        den += p;
        acc.x = fmaf(p, hv.x, acc.x); acc.y = fmaf(p, hv.y, acc.y);
        acc.z = fmaf(p, hv.z, acc.z); acc.w = fmaf(p, hv.w, acc.w);
    }

    #pragma unroll
    for (int off = 8; off <= 16; off <<= 1) {
        den   += __shfl_xor_sync(0xffffffffu, den,   off);
        acc.x += __shfl_xor_sync(0xffffffffu, acc.x, off);
        acc.y += __shfl_xor_sync(0xffffffffu, acc.y, off);
        acc.z += __shfl_xor_sync(0xffffffffu, acc.z, off);
        acc.w += __shfl_xor_sync(0xffffffffu, acc.w, off);
    }

    if (lane < 8) {
        float inv = 1.0f / (den + 1e-16f);
        float4 bb = *reinterpret_cast<const float4*>(b2 + coff);
        float4 o;
        o.x = fmaf(acc.x, inv, bb.x);
        o.y = fmaf(acc.y, inv, bb.y);
        o.z = fmaf(acc.z, inv, bb.z);
        o.w = fmaf(acc.w, inv, bb.w);
        *reinterpret_cast<float4*>(out + (size_t)node * 32 + coff) = o;
    }
}

// ---------------------------------------------------------------------------
extern "C" void kernel_launch(void* const* d_in, const int* in_sizes, int n_in,
                              void* d_out, int out_size) {
    const float* x      = (const float*)d_in[0];
    const int*   ei     = (const int*)d_in[1];
    const float* W1     = (const float*)d_in[2];
    const float* a_src1 = (const float*)d_in[3];
    const float* a_dst1 = (const float*)d_in[4];
    const float* b1     = (const float*)d_in[5];
    const float* W2     = (const float*)d_in[6];
    const float* a_src2 = (const float*)d_in[7];
    const float* a_dst2 = (const float*)d_in[8];
    const float* b2     = (const float*)d_in[9];
    float* out = (float*)d_out;

    const int n  = in_sizes[0] / 128;   // 50000
    const int E  = in_sizes[1] / 2;     // 1600000
    const int e8 = (E + 7) / 8;

    // One-time side stream + fork/join events (host objects; no device alloc).
    static cudaStream_t s2 = nullptr;
    static cudaEvent_t evFork = nullptr, evJoin = nullptr;
    if (!s2) {
        cudaStreamCreateWithFlags(&s2, cudaStreamNonBlocking);
        cudaEventCreateWithFlags(&evFork, cudaEventDisableTiming);
        cudaEventCreateWithFlags(&evJoin, cudaEventDisableTiming);
    }

    // Fork: graph chain (zero+scatter+W2 pack) on s2, feature chain (gemm1) on default.
    cudaEventRecord(evFork, 0);
    cudaStreamWaitEvent(s2, evFork, 0);
    zero_wr_kernel<<<(n + 255) / 256, 256, 0, s2>>>(n);
    pack_w2_kernel<<<8, 256, 0, s2>>>(W2);
    scatter_kernel<<<(e8 + 255) / 256, 256, 0, s2>>>(ei, E);
    cudaEventRecord(evJoin, s2);

    gemm1_kernel<<<(n + 63) / 64, 256>>>(x, W1, a_src1, a_dst1, n);

    // Join: fused agg1 needs gemm1 (stream order), scatter + W2p (event).
    cudaStreamWaitEvent(0, evJoin, 0);
    agg1_kernel<<<(n * 32 + 255) / 256, 256>>>(b1, a_src2, a_dst2, n);

    agg2_kernel<<<(n * 32 + 255) / 256, 256>>>(b2, n, out);
}

// round 13
// speedup vs baseline: 1.2578x; 1.0970x over previous
#include <cuda_runtime.h>
#include <cstdint>

#define MAXN 50000
#define MAXE 1600000
#define CAP  128   // bucket capacity per dst; Poisson(32) max-degree ~65, 2x margin

// Scratch (device globals — no allocation allowed)
__device__ __align__(16) float g_h1[MAXN * 64];    // layer1 features fp32
__device__ __align__(16) float g_es1[MAXN * 2];
__device__ __align__(16) float g_ed1[MAXN * 2];
__device__ __align__(16) float g_h2[MAXN * 32];    // layer2 features fp32
__device__ __align__(16) float g_es2[MAXN];
__device__ __align__(16) float g_ed2[MAXN];
__device__ __align__(16) float g_W2p[2048];        // packed W2: [k4*128 + j*4 + m] = W2[4k4+m][j]

// Bucketed adjacency (by destination); self-loops handled inline in agg
__device__ int g_wr[MAXN];            // per-dst fill counter (= in-degree)
__device__ int g_srt[MAXN * CAP];     // src ids, bucket d at [d*CAP, d*CAP+deg)

static __device__ __forceinline__ float lrelu(float v) {
    return v > 0.0f ? v : 0.2f * v;
}

// ---- packed f32x2 helpers (sm_103a 2x fp32 path) ----
static __device__ __forceinline__ unsigned long long dup2(float v) {
    unsigned long long r; unsigned u = __float_as_uint(v);
    asm("mov.b64 %0, {%1, %1};" : "=l"(r) : "r"(u));
    return r;
}
static __device__ __forceinline__ unsigned long long fma2(
    unsigned long long a, unsigned long long b, unsigned long long c) {
    unsigned long long d;
    asm("fma.rn.f32x2 %0, %1, %2, %3;" : "=l"(d) : "l"(a), "l"(b), "l"(c));
    return d;
}
static __device__ __forceinline__ float2 unpk(unsigned long long v) {
    unsigned lo, hi;
    asm("mov.b64 {%0, %1}, %2;" : "=r"(lo), "=r"(hi) : "l"(v));
    return make_float2(__uint_as_float(lo), __uint_as_float(hi));
}

// ---------------------------------------------------------------------------
__global__ void zero_wr_kernel(int n) {
    int i = blockIdx.x * blockDim.x + threadIdx.x;
    if (i < n) g_wr[i] = 0;
}

__global__ void pack_w2_kernel(const float* __restrict__ W2) {
    int idx = blockIdx.x * blockDim.x + threadIdx.x;
    if (idx >= 2048) return;
    int k4 = idx >> 7, j = (idx >> 2) & 31, m = idx & 3;
    g_W2p[idx] = W2[(4 * k4 + m) * 32 + j];
}

// ---------------------------------------------------------------------------
// Scatter edges into fixed-capacity dst buckets (8 edges/thread, MLP 8)
// ---------------------------------------------------------------------------
__global__ void scatter_kernel(const int* __restrict__ ei, int E) {
    int base = (blockIdx.x * blockDim.x + threadIdx.x) * 8;
    if (base + 8 <= E) {
        int4 sa = *reinterpret_cast<const int4*>(ei + base);
        int4 sb = *reinterpret_cast<const int4*>(ei + base + 4);
        int4 da = *reinterpret_cast<const int4*>(ei + E + base);
        int4 db = *reinterpret_cast<const int4*>(ei + E + base + 4);
        int p0 = atomicAdd(&g_wr[da.x], 1);
        int p1 = atomicAdd(&g_wr[da.y], 1);
        int p2 = atomicAdd(&g_wr[da.z], 1);
        int p3 = atomicAdd(&g_wr[da.w], 1);
        int p4 = atomicAdd(&g_wr[db.x], 1);
        int p5 = atomicAdd(&g_wr[db.y], 1);
        int p6 = atomicAdd(&g_wr[db.z], 1);
        int p7 = atomicAdd(&g_wr[db.w], 1);
        if (p0 < CAP) g_srt[da.x * CAP + p0] = sa.x;
        if (p1 < CAP) g_srt[da.y * CAP + p1] = sa.y;
        if (p2 < CAP) g_srt[da.z * CAP + p2] = sa.z;
        if (p3 < CAP) g_srt[da.w * CAP + p3] = sa.w;
        if (p4 < CAP) g_srt[db.x * CAP + p4] = sb.x;
        if (p5 < CAP) g_srt[db.y * CAP + p5] = sb.y;
        if (p6 < CAP) g_srt[db.z * CAP + p6] = sb.z;
        if (p7 < CAP) g_srt[db.w * CAP + p7] = sb.w;
    } else {
        for (int k = base; k < E; k++) {
            int d = ei[E + k];
            int p = atomicAdd(&g_wr[d], 1);
            if (p < CAP) g_srt[d * CAP + p] = ei[k];
        }
    }
}

// ---------------------------------------------------------------------------
// GEMM1 + scores1 fused: h1[N,64] = x[N,128] @ W1[128,64] (f32x2 FMA).
// BM=128, BN=64, BK=16; 256 threads as 16x16 grid; 8x4 per thread
// (1.5 smem bytes per FMA). Per-head scores in epilogue.
// ---------------------------------------------------------------------------
__global__ void gemm1_kernel(const float* __restrict__ x, const float* __restrict__ W,
                             const float* __restrict__ a_src, const float* __restrict__ a_dst,
                             int n) {
    __shared__ __align__(16) float As[16][128];
    __shared__ __align__(16) float Bs[16][64];
    const int t = threadIdx.x;
    const int row0 = blockIdx.x * 128;
    const int tr = t >> 4, tc = t & 15;            // 16x16 thread grid
    const int lm = t & 127, lk = (t >> 7) << 3;    // A-load: row lm, k lk..lk+7
    const int bk = t >> 4, bn = (t & 15) << 2;     // B-load
    unsigned long long acc2[8][2] = {};
    const int r = row0 + lm;

    for (int kt = 0; kt < 128; kt += 16) {
        float4 av0 = make_float4(0.f, 0.f, 0.f, 0.f);
        float4 av1 = make_float4(0.f, 0.f, 0.f, 0.f);
        if (r < n) {
            av0 = *reinterpret_cast<const float4*>(x + (size_t)r * 128 + kt + lk);
            av1 = *reinterpret_cast<const float4*>(x + (size_t)r * 128 + kt + lk + 4);
        }
        As[lk + 0][lm] = av0.x; As[lk + 1][lm] = av0.y;
        As[lk + 2][lm] = av0.z; As[lk + 3][lm] = av0.w;
        As[lk + 4][lm] = av1.x; As[lk + 5][lm] = av1.y;
        As[lk + 6][lm] = av1.z; As[lk + 7][lm] = av1.w;
        *reinterpret_cast<float4*>(&Bs[bk][bn]) =
            *reinterpret_cast<const float4*>(W + (size_t)(kt + bk) * 64 + bn);
        __syncthreads();
        #pragma unroll
        for (int kk = 0; kk < 16; kk++) {
            float4 aL = *reinterpret_cast<const float4*>(&As[kk][tr << 3]);
            float4 aH = *reinterpret_cast<const float4*>(&As[kk][(tr << 3) + 4]);
            unsigned long long b01 =
                *reinterpret_cast<const unsigned long long*>(&Bs[kk][tc << 2]);
            unsigned long long b23 =
                *reinterpret_cast<const unsigned long long*>(&Bs[kk][(tc << 2) + 2]);
            unsigned long long a0 = dup2(aL.x), a1 = dup2(aL.y),
                               a2 = dup2(aL.z), a3 = dup2(aL.w);
            unsigned long long a4 = dup2(aH.x), a5 = dup2(aH.y),
                               a6 = dup2(aH.z), a7 = dup2(aH.w);
            acc2[0][0] = fma2(a0, b01, acc2[0][0]); acc2[0][1] = fma2(a0, b23, acc2[0][1]);
            acc2[1][0] = fma2(a1, b01, acc2[1][0]); acc2[1][1] = fma2(a1, b23, acc2[1][1]);
            acc2[2][0] = fma2(a2, b01, acc2[2][0]); acc2[2][1] = fma2(a2, b23, acc2[2][1]);
            acc2[3][0] = fma2(a3, b01, acc2[3][0]); acc2[3][1] = fma2(a3, b23, acc2[3][1]);
            acc2[4][0] = fma2(a4, b01, acc2[4][0]); acc2[4][1] = fma2(a4, b23, acc2[4][1]);
            acc2[5][0] = fma2(a5, b01, acc2[5][0]); acc2[5][1] = fma2(a5, b23, acc2[5][1]);
            acc2[6][0] = fma2(a6, b01, acc2[6][0]); acc2[6][1] = fma2(a6, b23, acc2[6][1]);
            acc2[7][0] = fma2(a7, b01, acc2[7][0]); acc2[7][1] = fma2(a7, b23, acc2[7][1]);
        }
        __syncthreads();
    }

    float4 as4 = *reinterpret_cast<const float4*>(a_src + (tc << 2));
    float4 ad4 = *reinterpret_cast<const float4*>(a_dst + (tc << 2));
    #pragma unroll
    for (int i = 0; i < 8; i++) {
        float2 lo = unpk(acc2[i][0]);
        float2 hi = unpk(acc2[i][1]);
        int rr = row0 + (tr << 3) + i;
        if (rr < n)
            *reinterpret_cast<float4*>(g_h1 + (size_t)rr * 64 + (tc << 2)) =
                make_float4(lo.x, lo.y, hi.x, hi.y);
        float sp = lo.x * as4.x + lo.y * as4.y + hi.x * as4.z + hi.y * as4.w;
        float dp = lo.x * ad4.x + lo.y * ad4.y + hi.x * ad4.z + hi.y * ad4.w;
        #pragma unroll
        for (int off = 1; off < 8; off <<= 1) {
            sp += __shfl_xor_sync(0xffffffffu, sp, off);
            dp += __shfl_xor_sync(0xffffffffu, dp, off);
        }
        if ((tc & 7) == 0 && rr < n) {
            int head = tc >> 3;
            g_es1[rr * 2 + head] = sp;
            g_ed1[rr * 2 + head] = dp;
        }
    }
}

// ---------------------------------------------------------------------------
// agg1 + gemm2 + scores2 fused: one warp per dst node.
// Phase 1: 4 edges per 16-lane group iteration (i+=8, MLP ~12).
// Phase 2: feat in per-warp smem; W2 from pre-packed global (LDG.128), f32x2.
// ---------------------------------------------------------------------------
__global__ void agg1_kernel(const float* __restrict__ b1,
                            const float* __restrict__ a_src2,
                            const float* __restrict__ a_dst2, int n) {
    __shared__ __align__(16) float s_feat[8][64];

    int gid = blockIdx.x * blockDim.x + threadIdx.x;
    int node = gid >> 5, lane = gid & 31;
    int w = threadIdx.x >> 5;
    if (node >= n) return;

    const int grp = lane >> 4;
    const int sub = lane & 15;
    const int head = sub >> 3;
    const int coff = head * 32 + (sub & 7) * 4;
    const int* __restrict__ srt = g_srt;
    const float* __restrict__ es1 = g_es1;
    const float* __restrict__ h1 = g_h1;
    int deg = g_wr[node]; if (deg > CAP) deg = CAP;
    int beg = node * CAP, end = beg + deg;
    const float edh = g_ed1[2 * node + head];

    float den;
    float4 acc;
    {
        float p = __expf(lrelu(es1[2 * node + head] + edh));
        if (grp) p = 0.f;
        den = p;
        float4 hv = *reinterpret_cast<const float4*>(h1 + (size_t)node * 64 + coff);
        acc.x = p * hv.x; acc.y = p * hv.y; acc.z = p * hv.z; acc.w = p * hv.w;
    }

    int i = beg;
    for (; i + 8 <= end; i += 8) {
        int sA = srt[i + grp];
        int sB = srt[i + 2 + grp];
        int sC = srt[i + 4 + grp];
        int sD = srt[i + 6 + grp];
        float eA = es1[2 * sA + head];
        float eB = es1[2 * sB + head];
        float eC = es1[2 * sC + head];
        float eD = es1[2 * sD + head];
        float4 hA = *reinterpret_cast<const float4*>(h1 + (size_t)sA * 64 + coff);
        float4 hB = *reinterpret_cast<const float4*>(h1 + (size_t)sB * 64 + coff);
        float4 hC = *reinterpret_cast<const float4*>(h1 + (size_t)sC * 64 + coff);
        float4 hD = *reinterpret_cast<const float4*>(h1 + (size_t)sD * 64 + coff);
        float pA = __expf(lrelu(eA + edh));
        float pB = __expf(lrelu(eB + edh));
        float pC = __expf(lrelu(eC + edh));
        float pD = __expf(lrelu(eD + edh));
        den += pA + pB + pC + pD;
        acc.x = fmaf(pA, hA.x, acc.x); acc.y = fmaf(pA, hA.y, acc.y);
        acc.z = fmaf(pA, hA.z, acc.z); acc.w = fmaf(pA, hA.w, acc.w);
        acc.x = fmaf(pB, hB.x, acc.x); acc.y = fmaf(pB, hB.y, acc.y);
        acc.z = fmaf(pB, hB.z, acc.z); acc.w = fmaf(pB, hB.w, acc.w);
        acc.x = fmaf(pC, hC.x, acc.x); acc.y = fmaf(pC, hC.y, acc.y);
        acc.z = fmaf(pC, hC.z, acc.z); acc.w = fmaf(pC, hC.w, acc.w);
        acc.x = fmaf(pD, hD.x, acc.x); acc.y = fmaf(pD, hD.y, acc.y);
        acc.z = fmaf(pD, hD.z, acc.z); acc.w = fmaf(pD, hD.w, acc.w);
    }
    for (; i < end; i += 2) {
        int ii = i + grp;
        bool v = ii < end;
        int s = v ? srt[ii] : node;
        float e = es1[2 * s + head];
        float4 hv = *reinterpret_cast<const float4*>(h1 + (size_t)s * 64 + coff);
        float p = v ? __expf(lrelu(e + edh)) : 0.f;
        den += p;
        acc.x = fmaf(p, hv.x, acc.x); acc.y = fmaf(p, hv.y, acc.y);
        acc.z = fmaf(p, hv.z, acc.z); acc.w = fmaf(p, hv.w, acc.w);
    }

    den   += __shfl_xor_sync(0xffffffffu, den,   16);
    acc.x += __shfl_xor_sync(0xffffffffu, acc.x, 16);
    acc.y += __shfl_xor_sync(0xffffffffu, acc.y, 16);
    acc.z += __shfl_xor_sync(0xffffffffu, acc.z, 16);
    acc.w += __shfl_xor_sync(0xffffffffu, acc.w, 16);

    if (lane < 16) {
        float inv = 1.0f / (den + 1e-16f);
        float4 bb = *reinterpret_cast<const float4*>(b1 + coff);
        float4 o;
        o.x = fmaf(acc.x, inv, bb.x); o.x = o.x > 0.f ? o.x : 0.f;
        o.y = fmaf(acc.y, inv, bb.y); o.y = o.y > 0.f ? o.y : 0.f;
        o.z = fmaf(acc.z, inv, bb.z); o.z = o.z > 0.f ? o.z : 0.f;
        o.w = fmaf(acc.w, inv, bb.w); o.w = o.w > 0.f ? o.w : 0.f;
        *reinterpret_cast<float4*>(&s_feat[w][coff]) = o;
    }
    __syncwarp();

    // gemm2: h2[lane] = sum_k feat[k] * W2[k][lane]; W2 pre-packed in global.
    unsigned long long sum2 = 0;
    const float* feat = s_feat[w];
    #pragma unroll
    for (int k4 = 0; k4 < 16; k4++) {
        ulonglong2 a2 = *reinterpret_cast<const ulonglong2*>(feat + (k4 << 2));
        ulonglong2 w2 = *reinterpret_cast<const ulonglong2*>(g_W2p + (k4 << 7) + (lane << 2));
        sum2 = fma2(a2.x, w2.x, sum2);
        sum2 = fma2(a2.y, w2.y, sum2);
    }
    float2 sh = unpk(sum2);
    float sum = sh.x + sh.y;
    g_h2[(size_t)node * 32 + lane] = sum;

    float s = sum * a_src2[lane];
    float d = sum * a_dst2[lane];
    #pragma unroll
    for (int off = 16; off; off >>= 1) {
        s += __shfl_xor_sync(0xffffffffu, s, off);
        d += __shfl_xor_sync(0xffffffffu, d, off);
    }
    if (lane == 0) { g_es2[node] = s; g_ed2[node] = d; }
}

// ---------------------------------------------------------------------------
// agg2: one warp per dst; 16 edges per iteration (4 per 8-lane group)
// ---------------------------------------------------------------------------
__global__ void agg2_kernel(const float* __restrict__ b2, int n, float* __restrict__ out) {
    int gid = blockIdx.x * blockDim.x + threadIdx.x;
    int node = gid >> 5, lane = gid & 31;
    if (node >= n) return;
    const int grp = lane >> 3;
    const int coff = (lane & 7) * 4;
    const int* __restrict__ srt = g_srt;
    const float* __restrict__ es2 = g_es2;
    const float* __restrict__ h2 = g_h2;
    int deg = g_wr[node]; if (deg > CAP) deg = CAP;
    int beg = node * CAP, end = beg + deg;
    float edv = g_ed2[node];

    float den;
    float4 acc;
    {
        float p = __expf(lrelu(es2[node] + edv));
        if (grp) p = 0.f;
        den = p;
        float4 hv = *reinterpret_cast<const float4*>(h2 + (size_t)node * 32 + coff);
        acc.x = p * hv.x; acc.y = p * hv.y; acc.z = p * hv.z; acc.w = p * hv.w;
    }

    int i = beg;
    for (; i + 16 <= end; i += 16) {
        int sA = srt[i + grp];
        int sB = srt[i + 4 + grp];
        int sC = srt[i + 8 + grp];
        int sD = srt[i + 12 + grp];
        float eA = es2[sA], eB = es2[sB], eC = es2[sC], eD = es2[sD];
        float4 hA = *reinterpret_cast<const float4*>(h2 + (size_t)sA * 32 + coff);
        float4 hB = *reinterpret_cast<const float4*>(h2 + (size_t)sB * 32 + coff);
        float4 hC = *reinterpret_cast<const float4*>(h2 + (size_t)sC * 32 + coff);
        float4 hD = *reinterpret_cast<const float4*>(h2 + (size_t)sD * 32 + coff);
        float pA = __expf(lrelu(eA + edv));
        float pB = __expf(lrelu(eB + edv));
        float pC = __expf(lrelu(eC + edv));
        float pD = __expf(lrelu(eD + edv));
        den += pA + pB + pC + pD;
        acc.x = fmaf(pA, hA.x, acc.x); acc.y = fmaf(pA, hA.y, acc.y);
        acc.z = fmaf(pA, hA.z, acc.z); acc.w = fmaf(pA, hA.w, acc.w);
        acc.x = fmaf(pB, hB.x, acc.x); acc.y = fmaf(pB, hB.y, acc.y);
        acc.z = fmaf(pB, hB.z, acc.z); acc.w = fmaf(pB, hB.w, acc.w);
        acc.x = fmaf(pC, hC.x, acc.x); acc.y = fmaf(pC, hC.y, acc.y);
        acc.z = fmaf(pC, hC.z, acc.z); acc.w = fmaf(pC, hC.w, acc.w);
        acc.x = fmaf(pD, hD.x, acc.x); acc.y = fmaf(pD, hD.y, acc.y);
        acc.z = fmaf(pD, hD.z, acc.z); acc.w = fmaf(pD, hD.w, acc.w);
    }
    for (; i < end; i += 4) {
        int ii = i + grp;
        bool v = ii < end;
        int s = v ? srt[ii] : node;
        float e = es2[s];
        float4 hv = *reinterpret_cast<const float4*>(h2 + (size_t)s * 32 + coff);
        float p = v ? __expf(lrelu(e + edv)) : 0.f;
        den += p;
        acc.x = fmaf(p, hv.x, acc.x); acc.y = fmaf(p, hv.y, acc.y);
        acc.z = fmaf(p, hv.z, acc.z); acc.w = fmaf(p, hv.w, acc.w);
    }

    #pragma unroll
    for (int off = 8; off <= 16; off <<= 1) {
        den   += __shfl_xor_sync(0xffffffffu, den,   off);
        acc.x += __shfl_xor_sync(0xffffffffu, acc.x, off);
        acc.y += __shfl_xor_sync(0xffffffffu, acc.y, off);
        acc.z += __shfl_xor_sync(0xffffffffu, acc.z, off);
        acc.w += __shfl_xor_sync(0xffffffffu, acc.w, off);
    }

    if (lane < 8) {
        float inv = 1.0f / (den + 1e-16f);
        float4 bb = *reinterpret_cast<const float4*>(b2 + coff);
        float4 o;
        o.x = fmaf(acc.x, inv, bb.x);
        o.y = fmaf(acc.y, inv, bb.y);
        o.z = fmaf(acc.z, inv, bb.z);
        o.w = fmaf(acc.w, inv, bb.w);
        *reinterpret_cast<float4*>(out + (size_t)node * 32 + coff) = o;
    }
}

// ---------------------------------------------------------------------------
extern "C" void kernel_launch(void* const* d_in, const int* in_sizes, int n_in,
                              void* d_out, int out_size) {
    const float* x      = (const float*)d_in[0];
    const int*   ei     = (const int*)d_in[1];
    const float* W1     = (const float*)d_in[2];
    const float* a_src1 = (const float*)d_in[3];
    const float* a_dst1 = (const float*)d_in[4];
    const float* b1     = (const float*)d_in[5];
    const float* W2     = (const float*)d_in[6];
    const float* a_src2 = (const float*)d_in[7];
    const float* a_dst2 = (const float*)d_in[8];
    const float* b2     = (const float*)d_in[9];
    float* out = (float*)d_out;

    const int n  = in_sizes[0] / 128;   // 50000
    const int E  = in_sizes[1] / 2;     // 1600000
    const int e8 = (E + 7) / 8;

    static cudaStream_t s2 = nullptr;
    static cudaEvent_t evFork = nullptr, evJoin = nullptr;
    if (!s2) {
        cudaStreamCreateWithFlags(&s2, cudaStreamNonBlocking);
        cudaEventCreateWithFlags(&evFork, cudaEventDisableTiming);
        cudaEventCreateWithFlags(&evJoin, cudaEventDisableTiming);
    }

    cudaEventRecord(evFork, 0);
    cudaStreamWaitEvent(s2, evFork, 0);
    zero_wr_kernel<<<(n + 255) / 256, 256, 0, s2>>>(n);
    pack_w2_kernel<<<8, 256, 0, s2>>>(W2);
    scatter_kernel<<<(e8 + 255) / 256, 256, 0, s2>>>(ei, E);
    cudaEventRecord(evJoin, s2);

    gemm1_kernel<<<(n + 127) / 128, 256>>>(x, W1, a_src1, a_dst1, n);

    cudaStreamWaitEvent(0, evJoin, 0);
    agg1_kernel<<<(n * 32 + 255) / 256, 256>>>(b1, a_src2, a_dst2, n);

    agg2_kernel<<<(n * 32 + 255) / 256, 256>>>(b2, n, out);
}